// round 3
// baseline (speedup 1.0000x reference)
#include <cuda_runtime.h>

// memoryClusterer: superpixel gather + per-class contrast maps.
//   d_in[0] spx       int32 [1,1,1080,1920]
//   d_in[1] knn_pred  int32 [2000]
//   d_in[2] knn_dist  f32   [2000,8]
//   d_in[3] cent_dist f32   [2000,8]
//   out (f32): [preseg (HW)] ++ [attmaps (7,4,H,W)]
//     plane (a,k): a=0..6 (class j=a+1); k: 0=knn_att[j], 1=knn_contrast,
//                                        2=cent_att[j], 3=cent_contrast
// contrast_j = max over channels != j = (argmax==j ? max2 : max1).
//
// R3: persistent blocks, tables staged in smem (row stride 20 words = 80B so
// random-row LDS.128 spreads across all 8 bank groups). Kills the divergent
// LDG gather wavefronts that were saturating L1tex; DRAM write stream becomes
// the only binder.

static constexpr int HW  = 1080 * 1920;   // 2,073,600
static constexpr int S   = 2000;
static constexpr int NC  = 8;
static constexpr int ROW = 20;            // words per smem row (16 data + pred + 3 pad)
static constexpr int SMEM_BYTES = S * ROW * 4;   // 160,000 B
static constexpr int NTHREADS = 1024;

__device__ __forceinline__ void max2of8(const float v[NC], float& m1, float& m2, int& arg) {
    m1 = v[0];
    m2 = __int_as_float(0xff800000);  // -inf
    arg = 0;
#pragma unroll
    for (int c = 1; c < NC; c++) {
        float x = v[c];
        if (x > m1) { m2 = m1; m1 = x; arg = c; }
        else if (x > m2) { m2 = x; }
    }
}

__global__ __launch_bounds__(NTHREADS, 1)
void memory_clusterer_kernel(const int* __restrict__ spx,
                             const int* __restrict__ knn_pred,
                             const float4* __restrict__ knn_dist4,
                             const float4* __restrict__ cent_dist4,
                             float* __restrict__ out) {
    extern __shared__ float s_tab[];   // [S][ROW]

    // ---- stage tables: 16 data floats + pred per row ----
    for (int r = threadIdx.x; r < S; r += NTHREADS) {
        float4 a = __ldg(knn_dist4 + 2 * r);
        float4 b = __ldg(knn_dist4 + 2 * r + 1);
        float4 c = __ldg(cent_dist4 + 2 * r);
        float4 d = __ldg(cent_dist4 + 2 * r + 1);
        float p = (float)__ldg(knn_pred + r);
        float* row = s_tab + r * ROW;
        *reinterpret_cast<float4*>(row)      = a;
        *reinterpret_cast<float4*>(row + 4)  = b;
        *reinterpret_cast<float4*>(row + 8)  = c;
        *reinterpret_cast<float4*>(row + 12) = d;
        row[16] = p;
    }
    __syncthreads();

    const int stride = gridDim.x * NTHREADS;
    for (int i = blockIdx.x * NTHREADS + threadIdx.x; i < HW; i += stride) {
        const int idx = __ldg(spx + i) - 1;
        const float* row = s_tab + idx * ROW;

        const float4 ka = *reinterpret_cast<const float4*>(row);
        const float4 kb = *reinterpret_cast<const float4*>(row + 4);
        const float4 ca = *reinterpret_cast<const float4*>(row + 8);
        const float4 cb = *reinterpret_cast<const float4*>(row + 12);

        out[i] = row[16];
        float* base = out + HW + i;

        // ---- knn planes (k = 0,1) ----
        {
            float v[NC] = {ka.x, ka.y, ka.z, ka.w, kb.x, kb.y, kb.z, kb.w};
            float m1, m2; int arg;
            max2of8(v, m1, m2, arg);
#pragma unroll
            for (int a = 0; a < 7; a++) {
                const int j = a + 1;
                base[(size_t)(a * 4 + 0) * HW] = v[j];
                base[(size_t)(a * 4 + 1) * HW] = (arg == j) ? m2 : m1;
            }
        }

        // ---- cent planes (k = 2,3) ----
        {
            float v[NC] = {ca.x, ca.y, ca.z, ca.w, cb.x, cb.y, cb.z, cb.w};
            float m1, m2; int arg;
            max2of8(v, m1, m2, arg);
#pragma unroll
            for (int a = 0; a < 7; a++) {
                const int j = a + 1;
                base[(size_t)(a * 4 + 2) * HW] = v[j];
                base[(size_t)(a * 4 + 3) * HW] = (arg == j) ? m2 : m1;
            }
        }
    }
}

extern "C" void kernel_launch(void* const* d_in, const int* in_sizes, int n_in,
                              void* d_out, int out_size) {
    const int* spx = (const int*)d_in[0];
    const int* knn_pred = (const int*)d_in[1];
    const float4* knn_dist4 = (const float4*)d_in[2];
    const float4* cent_dist4 = (const float4*)d_in[3];
    float* out = (float*)d_out;

    static int n_sms = 0;
    if (n_sms == 0) {
        int dev = 0;
        cudaGetDevice(&dev);
        cudaDeviceGetAttribute(&n_sms, cudaDevAttrMultiProcessorCount, dev);
        cudaFuncSetAttribute(memory_clusterer_kernel,
                             cudaFuncAttributeMaxDynamicSharedMemorySize, SMEM_BYTES);
    }

    memory_clusterer_kernel<<<n_sms, NTHREADS, SMEM_BYTES>>>(
        spx, knn_pred, knn_dist4, cent_dist4, out);
}